// round 2
// baseline (speedup 1.0000x reference)
#include <cuda_runtime.h>

#define BATCH 2048
#define NE    2048
#define NDIMS 128
#define SPEC_C 6.5f

#define TILE   128
#define DCHUNK 32

// Scratch (device globals: allocation-free rule)
__device__ float g_xs[BATCH * NDIMS];   // attn-scaled inputs
__device__ float g_es[NE * NDIMS];      // attn-scaled exemplars
__device__ float g_sumx[BATCH];         // -C * row sums of g_xs
__device__ float g_sume[NE];            // -C * row sums of g_es

// ---------------------------------------------------------------------------
// Pre-scale: Xs = attn*X, Es = attn*E, plus per-row sums scaled by -C.
// One warp per row.
// ---------------------------------------------------------------------------
__global__ void prep_kernel(const float* __restrict__ X,
                            const float* __restrict__ E,
                            const float* __restrict__ attn) {
    const int warp = threadIdx.x >> 5;
    const int lane = threadIdx.x & 31;
    const int row  = blockIdx.x * 8 + warp;

    const float* src  = blockIdx.y ? E : X;
    float*       dst  = blockIdx.y ? g_es : g_xs;
    float*       dsum = blockIdx.y ? g_sume : g_sumx;

    float4 x = reinterpret_cast<const float4*>(src + (size_t)row * NDIMS)[lane];
    float4 a = reinterpret_cast<const float4*>(attn)[lane];
    float4 s = make_float4(x.x * a.x, x.y * a.y, x.z * a.z, x.w * a.w);
    reinterpret_cast<float4*>(dst + (size_t)row * NDIMS)[lane] = s;

    float t = (s.x + s.y) + (s.z + s.w);
    #pragma unroll
    for (int off = 16; off > 0; off >>= 1)
        t += __shfl_xor_sync(0xffffffffu, t, off);
    if (lane == 0) dsum[row] = -SPEC_C * t;
}

// ---------------------------------------------------------------------------
// Main: out[b,e] = exp( -C*SumX[b] + -C*SumE[e] + 2C * sum_d min(Xs,Es) )
// 128x128 tile / block, 256 threads, 8x8 micro-tile per thread.
// smem tiles stored transposed [d][row] with a 16B-granule XOR swizzle
// (group ^= d&7): conflict-free scalar STS AND aligned conflict-free LDS.128.
// Inner op pair: FMNMX (alu pipe, rt2) + FFMA-imm x13.0 (fma pipe, rt1).
// ---------------------------------------------------------------------------
__global__ __launch_bounds__(256, 2)
void alcove_kernel(float* __restrict__ out) {
    __shared__ float sx[DCHUNK * TILE];
    __shared__ float se[DCHUNK * TILE];

    const int tid = threadIdx.x;
    const int tx  = tid & 15;
    const int ty  = tid >> 4;
    const int b0  = blockIdx.y * TILE;
    const int e0  = blockIdx.x * TILE;

    float acc[8][8];
    #pragma unroll
    for (int i = 0; i < 8; ++i)
        #pragma unroll
        for (int j = 0; j < 8; ++j) acc[i][j] = 0.f;

    // staging decomposition: thread -> (q = d-quad, r = row-within-32)
    const int q = tid & 7;
    const int r = tid >> 3;

    for (int dc = 0; dc < NDIMS; dc += DCHUNK) {
        __syncthreads();
        // Stage gmem [row][d] -> smem [d][swizzled row-group] (transpose)
        #pragma unroll
        for (int p = 0; p < 4; ++p) {
            const int row = r + p * 32;
            const float4 vx = *reinterpret_cast<const float4*>(
                &g_xs[(size_t)(b0 + row) * NDIMS + dc + q * 4]);
            const float4 ve = *reinterpret_cast<const float4*>(
                &g_es[(size_t)(e0 + row) * NDIMS + dc + q * 4]);
            const float xa[4] = {vx.x, vx.y, vx.z, vx.w};
            const float ea[4] = {ve.x, ve.y, ve.z, ve.w};
            #pragma unroll
            for (int k = 0; k < 4; ++k) {
                const int d   = q * 4 + k;
                const int grp = (row >> 2) ^ (d & 7);      // XOR swizzle, 16B granule
                sx[d * TILE + grp * 4 + (row & 3)] = xa[k];
                se[d * TILE + grp * 4 + (row & 3)] = ea[k];
            }
        }
        __syncthreads();

        #pragma unroll 4
        for (int d = 0; d < DCHUNK; ++d) {
            const int w  = d & 7;
            const int gx = ty ^ w;
            const int ge = tx ^ w;
            const float4 xa = *reinterpret_cast<const float4*>(&sx[d * TILE + gx * 4]);
            const float4 xb = *reinterpret_cast<const float4*>(&sx[d * TILE + (16 + gx) * 4]);
            const float4 ea = *reinterpret_cast<const float4*>(&se[d * TILE + ge * 4]);
            const float4 eb = *reinterpret_cast<const float4*>(&se[d * TILE + (16 + ge) * 4]);
            const float xv[8] = {xa.x, xa.y, xa.z, xa.w, xb.x, xb.y, xb.z, xb.w};
            const float ev[8] = {ea.x, ea.y, ea.z, ea.w, eb.x, eb.y, eb.z, eb.w};
            #pragma unroll
            for (int i = 0; i < 8; ++i)
                #pragma unroll
                for (int j = 0; j < 8; ++j)
                    // FMNMX (alu) + FFMA-imm 2C (fma, rt1)
                    acc[i][j] = fmaf(fminf(xv[i], ev[j]), 2.0f * SPEC_C, acc[i][j]);
        }
    }

    // Epilogue: out = exp( sxc[b] + sec[e] + acc )   (sums pre-scaled by -C)
    float sxr[8], ser[8];
    #pragma unroll
    for (int i = 0; i < 8; ++i) {
        const int ri = (i < 4) ? (ty * 4 + i) : (64 + ty * 4 + (i - 4));
        sxr[i] = g_sumx[b0 + ri];
    }
    #pragma unroll
    for (int j = 0; j < 8; ++j) {
        const int cj = (j < 4) ? (tx * 4 + j) : (64 + tx * 4 + (j - 4));
        ser[j] = g_sume[e0 + cj];
    }

    #pragma unroll
    for (int i = 0; i < 8; ++i) {
        const int ri = (i < 4) ? (ty * 4 + i) : (64 + ty * 4 + (i - 4));
        float res[8];
        #pragma unroll
        for (int j = 0; j < 8; ++j) {
            const float arg = (sxr[i] + ser[j]) + acc[i][j];
            res[j] = __expf(arg);
        }
        float* orow = out + (size_t)(b0 + ri) * NE + e0;
        *reinterpret_cast<float4*>(&orow[tx * 4])      = make_float4(res[0], res[1], res[2], res[3]);
        *reinterpret_cast<float4*>(&orow[64 + tx * 4]) = make_float4(res[4], res[5], res[6], res[7]);
    }
}

// ---------------------------------------------------------------------------
extern "C" void kernel_launch(void* const* d_in, const int* in_sizes, int n_in,
                              void* d_out, int out_size) {
    const float* X    = (const float*)d_in[0];  // (2048,128)
    const float* E    = (const float*)d_in[1];  // (2048,128)
    const float* attn = (const float*)d_in[2];  // (128,)
    float* out = (float*)d_out;                 // (2048,2048)

    dim3 gprep(BATCH / 8, 2);
    prep_kernel<<<gprep, 256>>>(X, E, attn);

    dim3 gmain(NE / TILE, BATCH / TILE);
    alcove_kernel<<<gmain, 256>>>(out);
}

// round 3
// speedup vs baseline: 1.1098x; 1.1098x over previous
#include <cuda_runtime.h>

#define BATCH 2048
#define NE    2048
#define NDIMS 128
#define SPEC_C 6.5f

#define TILE   128
#define DCHUNK 32
#define SROW   132   // padded smem row stride (floats): LDS.128-aligned, conflict-free compute loads

// Scratch (device globals: allocation-free rule)
__device__ float g_xs[BATCH * NDIMS];   // attn-scaled inputs
__device__ float g_es[NE * NDIMS];      // attn-scaled exemplars
__device__ float g_sumx[BATCH];         // -C * row sums of g_xs
__device__ float g_sume[NE];            // -C * row sums of g_es

// ---------------------------------------------------------------------------
// Pre-scale: Xs = attn*X, Es = attn*E, plus per-row sums scaled by -C.
// ---------------------------------------------------------------------------
__global__ void prep_kernel(const float* __restrict__ X,
                            const float* __restrict__ E,
                            const float* __restrict__ attn) {
    const int warp = threadIdx.x >> 5;
    const int lane = threadIdx.x & 31;
    const int row  = blockIdx.x * 8 + warp;

    const float* src  = blockIdx.y ? E : X;
    float*       dst  = blockIdx.y ? g_es : g_xs;
    float*       dsum = blockIdx.y ? g_sume : g_sumx;

    float4 x = reinterpret_cast<const float4*>(src + (size_t)row * NDIMS)[lane];
    float4 a = reinterpret_cast<const float4*>(attn)[lane];
    float4 s = make_float4(x.x * a.x, x.y * a.y, x.z * a.z, x.w * a.w);
    reinterpret_cast<float4*>(dst + (size_t)row * NDIMS)[lane] = s;

    float t = (s.x + s.y) + (s.z + s.w);
    #pragma unroll
    for (int off = 16; off > 0; off >>= 1)
        t += __shfl_xor_sync(0xffffffffu, t, off);
    if (lane == 0) dsum[row] = -SPEC_C * t;
}

// Packed accumulate: acc(2 floats) += min-pair * (2C, 2C).  One FFMA2 on fma pipe.
__device__ __forceinline__ void ffma2_acc(unsigned long long& acc, float m0, float m1,
                                          unsigned long long k2) {
    asm("{\n\t"
        ".reg .b64 t;\n\t"
        "mov.b64 t, {%1, %2};\n\t"
        "fma.rn.f32x2 %0, t, %3, %0;\n\t"
        "}" : "+l"(acc) : "f"(m0), "f"(m1), "l"(k2));
}

// ---------------------------------------------------------------------------
// Main: out[b,e] = exp( -C*SumX[b] + -C*SumE[e] + 2C * sum_d min(Xs,Es) )
// 128x128 tile / block, 256 threads, 8x8 micro-tile per thread.
// smem [d][row] with SROW=132 padding (R1 layout, proven). Staging STS uses a
// k-rotation (k = (s + q/2) & 3) making warp STS banks injective -> conflict-free.
// Inner pair: FMNMX (alu pipe) + fma.rn.f32x2 (fma pipe, 2 elems/instr).
// ---------------------------------------------------------------------------
__global__ __launch_bounds__(256, 2)
void alcove_kernel(float* __restrict__ out) {
    __shared__ float sx[DCHUNK * SROW];
    __shared__ float se[DCHUNK * SROW];

    const int tid = threadIdx.x;
    const int tx  = tid & 15;
    const int ty  = tid >> 4;
    const int b0  = blockIdx.y * TILE;
    const int e0  = blockIdx.x * TILE;

    const unsigned long long K2 = 0x4150000041500000ULL;  // (13.0f, 13.0f) = 2*C

    unsigned long long acc[8][4];   // [i][j-pair], each packs 2 adjacent j
    #pragma unroll
    for (int i = 0; i < 8; ++i)
        #pragma unroll
        for (int jp = 0; jp < 4; ++jp) acc[i][jp] = 0ULL;

    // staging decomposition: thread -> (q = d-quad, r = row-within-32)
    const int q  = tid & 7;
    const int r  = tid >> 3;
    const int qh = q >> 1;

    for (int dc = 0; dc < NDIMS; dc += DCHUNK) {
        __syncthreads();
        // Stage gmem [row][d] -> smem [d][row] (transpose), conflict-free STS
        #pragma unroll
        for (int p = 0; p < 4; ++p) {
            const int row = r + p * 32;
            const float4 vx = *reinterpret_cast<const float4*>(
                &g_xs[(size_t)(b0 + row) * NDIMS + dc + q * 4]);
            const float4 ve = *reinterpret_cast<const float4*>(
                &g_es[(size_t)(e0 + row) * NDIMS + dc + q * 4]);
            const float xa[4] = {vx.x, vx.y, vx.z, vx.w};
            const float ea[4] = {ve.x, ve.y, ve.z, ve.w};
            #pragma unroll
            for (int s = 0; s < 4; ++s) {
                const int k = (s + qh) & 3;           // bank-rotation
                const int d = q * 4 + k;
                sx[d * SROW + row] = xa[k];
                se[d * SROW + row] = ea[k];
            }
        }
        __syncthreads();

        #pragma unroll 8
        for (int d = 0; d < DCHUNK; ++d) {
            const float4 xa = *reinterpret_cast<const float4*>(&sx[d * SROW + ty * 4]);
            const float4 xb = *reinterpret_cast<const float4*>(&sx[d * SROW + 64 + ty * 4]);
            const float4 ea = *reinterpret_cast<const float4*>(&se[d * SROW + tx * 4]);
            const float4 eb = *reinterpret_cast<const float4*>(&se[d * SROW + 64 + tx * 4]);
            const float xv[8] = {xa.x, xa.y, xa.z, xa.w, xb.x, xb.y, xb.z, xb.w};
            const float ev[8] = {ea.x, ea.y, ea.z, ea.w, eb.x, eb.y, eb.z, eb.w};
            #pragma unroll
            for (int i = 0; i < 8; ++i) {
                #pragma unroll
                for (int jp = 0; jp < 4; ++jp) {
                    const float m0 = fminf(xv[i], ev[2 * jp]);      // FMNMX (alu)
                    const float m1 = fminf(xv[i], ev[2 * jp + 1]);  // FMNMX (alu)
                    ffma2_acc(acc[i][jp], m0, m1, K2);              // FFMA2 (fma)
                }
            }
        }
    }

    // Epilogue: out = exp( sx[b] + se[e] + acc )   (sums pre-scaled by -C)
    float sxr[8], ser[8];
    #pragma unroll
    for (int i = 0; i < 8; ++i) {
        const int ri = (i < 4) ? (ty * 4 + i) : (64 + ty * 4 + (i - 4));
        sxr[i] = g_sumx[b0 + ri];
    }
    #pragma unroll
    for (int j = 0; j < 8; ++j) {
        const int cj = (j < 4) ? (tx * 4 + j) : (64 + tx * 4 + (j - 4));
        ser[j] = g_sume[e0 + cj];
    }

    #pragma unroll
    for (int i = 0; i < 8; ++i) {
        const int ri = (i < 4) ? (ty * 4 + i) : (64 + ty * 4 + (i - 4));
        float res[8];
        #pragma unroll
        for (int jp = 0; jp < 4; ++jp) {
            float lo, hi;
            asm("mov.b64 {%0, %1}, %2;" : "=f"(lo), "=f"(hi) : "l"(acc[i][jp]));
            res[2 * jp]     = __expf(sxr[i] + ser[2 * jp]     + lo);
            res[2 * jp + 1] = __expf(sxr[i] + ser[2 * jp + 1] + hi);
        }
        float* orow = out + (size_t)(b0 + ri) * NE + e0;
        *reinterpret_cast<float4*>(&orow[tx * 4])      = make_float4(res[0], res[1], res[2], res[3]);
        *reinterpret_cast<float4*>(&orow[64 + tx * 4]) = make_float4(res[4], res[5], res[6], res[7]);
    }
}

// ---------------------------------------------------------------------------
extern "C" void kernel_launch(void* const* d_in, const int* in_sizes, int n_in,
                              void* d_out, int out_size) {
    const float* X    = (const float*)d_in[0];  // (2048,128)
    const float* E    = (const float*)d_in[1];  // (2048,128)
    const float* attn = (const float*)d_in[2];  // (128,)
    float* out = (float*)d_out;                 // (2048,2048)

    dim3 gprep(BATCH / 8, 2);
    prep_kernel<<<gprep, 256>>>(X, E, attn);

    dim3 gmain(NE / TILE, BATCH / TILE);
    alcove_kernel<<<gmain, 256>>>(out);
}